// round 1
// baseline (speedup 1.0000x reference)
#include <cuda_runtime.h>

// ---------------------------------------------------------------------------
// GCNEdgePredictorWithEmbeddings — round 1 baseline (fp32 SIMT)
//
// Math refactor (avoids materializing a_norm [8192x8192]):
//   w      = relu(attn)                          (applied on the fly)
//   deg[j] = sum_i w[i,j] ; dis = rsqrt(deg) (0 if deg<=0)
//   A_norm^T @ Y  ==  dis ⊙ ( w^T @ (dis ⊙ Y) )
// Pipeline:
//   deg_partial -> dis
//   P = dis ⊙ (emb[node_idx] @ W1)                      [8192,256]
//   H = relu( dis ⊙ (w^T @ P) + b1 )                    [8192,256]
//   Q = dis ⊙ (H @ W2)                                  [8192,128]
//   Z = dis ⊙ (w^T @ Q) + b2                            [8192,128]
//   scores[e] = dot(Z[src[e]], Z[dst[e]])               [2M]
// ---------------------------------------------------------------------------

static constexpr int N_NODES = 8192;
static constexpr int E_DIM_C = 256;
static constexpr int HID_C   = 256;
static constexpr int OUT_C   = 128;

// Scratch (device globals: no allocation at kernel_launch time)
__device__ float g_degp[64 * N_NODES];        // partial column sums
__device__ float g_dis [N_NODES];
__device__ float g_P   [N_NODES * HID_C];
__device__ float g_H   [N_NODES * HID_C];
__device__ float g_Q   [N_NODES * OUT_C];
__device__ float g_Z   [N_NODES * OUT_C];

// ---------------------------------------------------------------------------
// deg: two-phase deterministic column-sum of relu(attn)
// grid (8, 64), block 256; each thread: 4 columns (float4) x 128 rows
// ---------------------------------------------------------------------------
__global__ void deg_partial_kernel(const float* __restrict__ attn)
{
    int c4 = blockIdx.x * blockDim.x + threadIdx.x;   // float4 column index
    int r0 = blockIdx.y * 128;
    float4 s = make_float4(0.f, 0.f, 0.f, 0.f);
    const float4* a = reinterpret_cast<const float4*>(attn);
    #pragma unroll 4
    for (int r = 0; r < 128; ++r) {
        float4 v = a[(size_t)(r0 + r) * (N_NODES / 4) + c4];
        s.x += fmaxf(v.x, 0.f);
        s.y += fmaxf(v.y, 0.f);
        s.z += fmaxf(v.z, 0.f);
        s.w += fmaxf(v.w, 0.f);
    }
    reinterpret_cast<float4*>(g_degp)[blockIdx.y * (N_NODES / 4) + c4] = s;
}

__global__ void dis_kernel()
{
    int col = blockIdx.x * blockDim.x + threadIdx.x;
    float s = 0.f;
    #pragma unroll
    for (int r = 0; r < 64; ++r) s += g_degp[r * N_NODES + col];
    g_dis[col] = (s > 0.f) ? rsqrtf(s) : 0.f;
}

// ---------------------------------------------------------------------------
// Generic fp32 tiled GEMM:  C[M,N] = epi( rowScale[m] * sum_k Aop[k,m]*B[k,n] )
//   TRANS_A: A is [K, M] row-major (lda = M-stride). used for w^T @ Y.
//   !TRANS_A: A is [M, K] row-major (lda = K).
//   RELU_A: relu applied to A elements on load (attn -> w)
//   GATHER_A: A rows indirected through gatherIdx (embedding lookup)
//   epi: optional +bias[n], optional relu
// BM=128, BN=64, BK=16, TM=8, TN=4 -> 256 threads, register-prefetch pipeline
// ---------------------------------------------------------------------------
template<int BM, int BN, int BK, int TM, int TN,
         bool TRANS_A, bool RELU_A, bool GATHER_A,
         bool HAS_BIAS, bool RELU_OUT>
__global__ __launch_bounds__((BM / TM) * (BN / TN))
void gemm_kernel(const float* __restrict__ A, int lda,
                 const float* __restrict__ B,
                 float* __restrict__ C,
                 const float* __restrict__ bias,
                 const float* __restrict__ rowScale,
                 const int*   __restrict__ gatherIdx,
                 int M, int N, int K)
{
    constexpr int NT   = (BM / TM) * (BN / TN);     // 256
    constexpr int APAD = 4;
    constexpr int AV   = (BM * BK) / (4 * NT);      // float4 A loads / thread
    constexpr int BV   = (BK * BN) / (4 * NT);      // float4 B loads / thread

    __shared__ float As[BK][BM + APAD];
    __shared__ float Bs[BK][BN];

    const int tid = threadIdx.x;
    const int tx  = tid % (BN / TN);
    const int ty  = tid / (BN / TN);
    const int m0  = blockIdx.y * BM;
    const int n0  = blockIdx.x * BN;

    float4 areg[AV];
    float4 breg[BV];

    float acc[TM][TN];
    #pragma unroll
    for (int i = 0; i < TM; ++i)
        #pragma unroll
        for (int j = 0; j < TN; ++j) acc[i][j] = 0.f;

    auto loadA = [&](int k0) {
        #pragma unroll
        for (int v = 0; v < AV; ++v) {
            int idx = tid + v * NT;
            float4 t;
            if (TRANS_A) {
                int k  = idx / (BM / 4);
                int m4 = idx % (BM / 4);
                t = *reinterpret_cast<const float4*>(A + (size_t)(k0 + k) * lda + (m0 + m4 * 4));
            } else {
                int m  = idx / (BK / 4);
                int kq = idx % (BK / 4);
                int row;
                if (GATHER_A) row = gatherIdx[m0 + m];
                else          row = m0 + m;
                t = *reinterpret_cast<const float4*>(A + (size_t)row * lda + (k0 + kq * 4));
            }
            if (RELU_A) {
                t.x = fmaxf(t.x, 0.f); t.y = fmaxf(t.y, 0.f);
                t.z = fmaxf(t.z, 0.f); t.w = fmaxf(t.w, 0.f);
            }
            areg[v] = t;
        }
    };

    auto storeA = [&]() {
        #pragma unroll
        for (int v = 0; v < AV; ++v) {
            int idx = tid + v * NT;
            if (TRANS_A) {
                int k  = idx / (BM / 4);
                int m4 = idx % (BM / 4);
                *reinterpret_cast<float4*>(&As[k][m4 * 4]) = areg[v];
            } else {
                int m  = idx / (BK / 4);
                int kq = idx % (BK / 4);
                As[kq * 4 + 0][m] = areg[v].x;
                As[kq * 4 + 1][m] = areg[v].y;
                As[kq * 4 + 2][m] = areg[v].z;
                As[kq * 4 + 3][m] = areg[v].w;
            }
        }
    };

    auto loadB = [&](int k0) {
        #pragma unroll
        for (int v = 0; v < BV; ++v) {
            int idx = tid + v * NT;
            int k  = idx / (BN / 4);
            int n4 = idx % (BN / 4);
            breg[v] = *reinterpret_cast<const float4*>(B + (size_t)(k0 + k) * N + (n0 + n4 * 4));
        }
    };

    auto storeB = [&]() {
        #pragma unroll
        for (int v = 0; v < BV; ++v) {
            int idx = tid + v * NT;
            int k  = idx / (BN / 4);
            int n4 = idx % (BN / 4);
            *reinterpret_cast<float4*>(&Bs[k][n4 * 4]) = breg[v];
        }
    };

    loadA(0); loadB(0);
    storeA(); storeB();
    __syncthreads();

    const int KT = K / BK;
    for (int kt = 0; kt < KT; ++kt) {
        if (kt + 1 < KT) { loadA((kt + 1) * BK); loadB((kt + 1) * BK); }

        #pragma unroll
        for (int kk = 0; kk < BK; ++kk) {
            float a[TM], b[TN];
            #pragma unroll
            for (int i = 0; i < TM; i += 4) {
                float4 t = *reinterpret_cast<const float4*>(&As[kk][ty * TM + i]);
                a[i] = t.x; a[i + 1] = t.y; a[i + 2] = t.z; a[i + 3] = t.w;
            }
            #pragma unroll
            for (int j = 0; j < TN; j += 4) {
                float4 t = *reinterpret_cast<const float4*>(&Bs[kk][tx * TN + j]);
                b[j] = t.x; b[j + 1] = t.y; b[j + 2] = t.z; b[j + 3] = t.w;
            }
            #pragma unroll
            for (int i = 0; i < TM; ++i)
                #pragma unroll
                for (int j = 0; j < TN; ++j)
                    acc[i][j] = fmaf(a[i], b[j], acc[i][j]);
        }

        if (kt + 1 < KT) {
            __syncthreads();
            storeA(); storeB();
            __syncthreads();
        }
    }

    // epilogue: C = maybe_relu( rowScale[m]*acc + bias[n] )
    #pragma unroll
    for (int i = 0; i < TM; ++i) {
        int row = m0 + ty * TM + i;
        float sc = rowScale[row];
        #pragma unroll
        for (int j = 0; j < TN; j += 4) {
            int col = n0 + tx * TN + j;
            float4 r;
            r.x = acc[i][j + 0] * sc;
            r.y = acc[i][j + 1] * sc;
            r.z = acc[i][j + 2] * sc;
            r.w = acc[i][j + 3] * sc;
            if (HAS_BIAS) {
                float4 bb = *reinterpret_cast<const float4*>(bias + col);
                r.x += bb.x; r.y += bb.y; r.z += bb.z; r.w += bb.w;
            }
            if (RELU_OUT) {
                r.x = fmaxf(r.x, 0.f); r.y = fmaxf(r.y, 0.f);
                r.z = fmaxf(r.z, 0.f); r.w = fmaxf(r.w, 0.f);
            }
            *reinterpret_cast<float4*>(C + (size_t)row * N + col) = r;
        }
    }
}

// ---------------------------------------------------------------------------
// Edge decode: one warp per edge. Z rows are 128 floats = 32 lanes x float4.
// ---------------------------------------------------------------------------
__global__ void decode_kernel(const int* __restrict__ eli,
                              float* __restrict__ out, int nPred)
{
    int warp = (blockIdx.x * blockDim.x + threadIdx.x) >> 5;
    int lane = threadIdx.x & 31;
    if (warp >= nPred) return;
    int s = eli[warp];
    int d = eli[nPred + warp];
    const float4* zs = reinterpret_cast<const float4*>(g_Z + (size_t)s * OUT_C);
    const float4* zd = reinterpret_cast<const float4*>(g_Z + (size_t)d * OUT_C);
    float4 a = zs[lane];
    float4 b = zd[lane];
    float dot = a.x * b.x + a.y * b.y + a.z * b.z + a.w * b.w;
    #pragma unroll
    for (int o = 16; o; o >>= 1) dot += __shfl_xor_sync(0xffffffffu, dot, o);
    if (lane == 0) out[warp] = dot;
}

// ---------------------------------------------------------------------------
extern "C" void kernel_launch(void* const* d_in, const int* in_sizes, int n_in,
                              void* d_out, int out_size)
{
    const int*   nodeIdx = (const int*)  d_in[0];
    const float* attn    = (const float*)d_in[1];
    const int*   eli     = (const int*)  d_in[2];
    const float* emb     = (const float*)d_in[3];
    const float* W1      = (const float*)d_in[4];
    const float* b1      = (const float*)d_in[5];
    const float* W2      = (const float*)d_in[6];
    const float* b2      = (const float*)d_in[7];
    float* out = (float*)d_out;
    const int nPred = in_sizes[2] / 2;

    float *pDis, *pP, *pH, *pQ, *pZ;
    cudaGetSymbolAddress((void**)&pDis, g_dis);
    cudaGetSymbolAddress((void**)&pP,   g_P);
    cudaGetSymbolAddress((void**)&pH,   g_H);
    cudaGetSymbolAddress((void**)&pQ,   g_Q);
    cudaGetSymbolAddress((void**)&pZ,   g_Z);

    // 1) deg / dis
    deg_partial_kernel<<<dim3(N_NODES / (256 * 4), 64), 256>>>(attn);
    dis_kernel<<<N_NODES / 256, 256>>>();

    // 2) P = dis ⊙ (emb[nodeIdx] @ W1)      [8192,256] (NN, gather)
    gemm_kernel<128, 64, 16, 8, 4, false, false, true, false, false>
        <<<dim3(HID_C / 64, N_NODES / 128), 256>>>(
            emb, E_DIM_C, W1, pP, nullptr, pDis, nodeIdx,
            N_NODES, HID_C, E_DIM_C);

    // 3) H = relu( dis ⊙ (relu(attn)^T @ P) + b1 )   [8192,256] (TN)
    gemm_kernel<128, 64, 16, 8, 4, true, true, false, true, true>
        <<<dim3(HID_C / 64, N_NODES / 128), 256>>>(
            attn, N_NODES, pP, pH, b1, pDis, nullptr,
            N_NODES, HID_C, N_NODES);

    // 4) Q = dis ⊙ (H @ W2)                  [8192,128] (NN)
    gemm_kernel<128, 64, 16, 8, 4, false, false, false, false, false>
        <<<dim3(OUT_C / 64, N_NODES / 128), 256>>>(
            pH, HID_C, W2, pQ, nullptr, pDis, nullptr,
            N_NODES, OUT_C, HID_C);

    // 5) Z = dis ⊙ (relu(attn)^T @ Q) + b2   [8192,128] (TN)
    gemm_kernel<128, 64, 16, 8, 4, true, true, false, true, false>
        <<<dim3(OUT_C / 64, N_NODES / 128), 256>>>(
            attn, N_NODES, pQ, pZ, b2, pDis, nullptr,
            N_NODES, OUT_C, N_NODES);

    // 6) decode: warp per edge
    {
        int warpsPerBlock = 8;                      // 256 threads
        int blocks = (nPred + warpsPerBlock - 1) / warpsPerBlock;
        decode_kernel<<<blocks, 256>>>(eli, out, nPred);
    }
}